// round 11
// baseline (speedup 1.0000x reference)
#include <cuda_runtime.h>
#include <cuda_bf16.h>

// ---------------- static scratch ----------------
__device__ int g_node_off[1025];

__global__ void k_prefix(const int* __restrict__ bn, int B) {
    if (threadIdx.x == 0) {
        int acc = 0;
        g_node_off[0] = 0;
        for (int i = 0; i < B; ++i) { acc += bn[i]; g_node_off[i + 1] = acc; }
    }
}

// ---------------- fast path ------------------------------------------------
// CTA = (graph, chunk); 4 warps, warp w owns 32-col slice [32w, 32w+32).
// Per-warp private accumulator: 64 segs x 32 floats (stride 32, conflict-free).
//
// R11: feature loads are consumed ONLY by rmw, one full iteration after
// issue (~600+cyc in-flight -> DRAM latency fully hidden with just 2 vv
// buffers / ~100 regs; R10's 3rd buffer spilled at the 128-reg cap).
//   plan = xy-only warp intrinsics (seg shfl, match, vote); packs segs
//          (8x8b), leader mask, rare mask, collision flags.
//   rmw  = 8x { shfl inv, predicated LDS.128 + 4xFFMA(v,inv,a) + STS.128 };
//          rare donor-merge (warp-uniform ~9% branch) relocated here.
#define FULLM 0xffffffffu

struct Meta { int seg; float inv; };                    // per-lane raw xy
struct Plan { unsigned sp0, sp1, pmask, cmask; };       // packed per-batch

__device__ __forceinline__ void load_xy(
    Meta& m, const int* __restrict__ xy, int base, int cend, int G, int lane)
{
    const int cnt = cend - base;                   // >= 1
    const int l   = (lane < cnt) ? lane : (cnt - 1);
    const int nd  = base + l;
    const int rr  = __ldg(&xy[3 * nd + 0]);
    const int cc  = __ldg(&xy[3 * nd + 1]);
    const int dv  = __ldg(&xy[3 * nd + 2]);
    m.seg = (lane < cnt) ? (rr * G + cc) : (64 + lane);   // marker never matches
    m.inv = 1.0f / (float)dv;
}

__device__ __forceinline__ void load_feat(
    float4 vv[8], const float* __restrict__ fbase, int base, int cend, int grp)
{
    const int cnt = cend - base;
    #pragma unroll
    for (int it = 0; it < 8; ++it) {
        const int nb   = it * 4 + grp;
        const int node = base + ((nb < cnt) ? nb : (cnt - 1));
        vv[it] = __ldg(reinterpret_cast<const float4*>(fbase + (size_t)node * 128));
    }
}

__device__ __forceinline__ void plan_batch(
    Plan& P, const Meta& m, int base, int cend, int lane, int grp, unsigned below)
{
    const int cnt = (cend - base >= 32) ? 32 : (cend - base);
    unsigned pm = 0, s0 = 0, s1 = 0, cm = 0;

    #pragma unroll
    for (int it = 0; it < 8; ++it) {
        const int      nb     = it * 4 + grp;
        const int      seg    = __shfl_sync(FULLM, m.seg, nb);
        const unsigned mm     = __match_any_sync(FULLM, seg);
        const bool     leader = (mm & below) == 0u;
        const bool     act    = (nb < cnt);

        const unsigned sb = (unsigned)(seg & 63) << ((it & 3) * 8);
        if (it < 4) s0 |= sb; else s1 |= sb;
        if (act && leader) pm |= (1u << it);

        if (!__all_sync(FULLM, leader)) {              // warp-uniform
            pm |= (1u << (8 + it));
            const unsigned c1 = ((grp < 3) && ((mm >> ((lane + 8)  & 31)) & 1u)) ? 1u : 0u;
            const unsigned c2 = ((grp < 2) && ((mm >> ((lane + 16) & 31)) & 1u)) ? 2u : 0u;
            const unsigned c3 = ((grp < 1) && ((mm >> ((lane + 24) & 31)) & 1u)) ? 4u : 0u;
            cm |= (c1 | c2 | c3) << (it * 3);
        }
    }
    P.sp0 = s0; P.sp1 = s1; P.pmask = pm; P.cmask = cm;
}

__device__ __forceinline__ void rmw_batch(
    float* __restrict__ acc, const float4 vv[8], const Plan& P, const Meta& m,
    int grp, int slot)
{
    #pragma unroll
    for (int it = 0; it < 8; ++it) {
        const int   nb  = it * 4 + grp;
        const float inv = __shfl_sync(FULLM, m.inv, nb);
        const unsigned sp  = (it < 4) ? P.sp0 : P.sp1;
        const int      seg = (sp >> ((it & 3) * 8)) & 0x3F;
        const bool lead = (P.pmask >> it) & 1u;
        const bool rare = (P.pmask >> (8 + it)) & 1u;    // warp-uniform

        float4* ap = reinterpret_cast<float4*>(acc + seg * 32 + slot * 4);
        const float4 v = vv[it];

        if (!rare) {                                    // ~91%
            if (lead) {
                float4 a = *ap;
                a.x = fmaf(v.x, inv, a.x);
                a.y = fmaf(v.y, inv, a.y);
                a.z = fmaf(v.z, inv, a.z);
                a.w = fmaf(v.w, inv, a.w);
                *ap = a;
            }
        } else {                                        // donor merge here
            float wx = v.x * inv, wy = v.y * inv, wz = v.z * inv, ww = v.w * inv;
            const float x1 = __shfl_down_sync(FULLM, wx, 8);
            const float y1 = __shfl_down_sync(FULLM, wy, 8);
            const float z1 = __shfl_down_sync(FULLM, wz, 8);
            const float w1 = __shfl_down_sync(FULLM, ww, 8);
            const float x2 = __shfl_down_sync(FULLM, wx, 16);
            const float y2 = __shfl_down_sync(FULLM, wy, 16);
            const float z2 = __shfl_down_sync(FULLM, wz, 16);
            const float w2 = __shfl_down_sync(FULLM, ww, 16);
            const float x3 = __shfl_down_sync(FULLM, wx, 24);
            const float y3 = __shfl_down_sync(FULLM, wy, 24);
            const float z3 = __shfl_down_sync(FULLM, wz, 24);
            const float w3 = __shfl_down_sync(FULLM, ww, 24);
            const unsigned cf = (P.cmask >> (it * 3)) & 7u;
            const bool c1 = cf & 1u, c2 = cf & 2u, c3 = cf & 4u;
            if (lead) {
                float4 a = *ap;
                a.x += wx + (c1 ? x1 : 0.f) + (c2 ? x2 : 0.f) + (c3 ? x3 : 0.f);
                a.y += wy + (c1 ? y1 : 0.f) + (c2 ? y2 : 0.f) + (c3 ? y3 : 0.f);
                a.z += wz + (c1 ? z1 : 0.f) + (c2 ? z2 : 0.f) + (c3 ? z3 : 0.f);
                a.w += ww + (c1 ? w1 : 0.f) + (c2 ? w2 : 0.f) + (c3 ? w3 : 0.f);
                *ap = a;
            }
        }
    }
}

__global__ void __launch_bounds__(128, 5) spp_pipe_kernel(
    const float* __restrict__ feat,
    const int*   __restrict__ xy,
    float*       __restrict__ out,
    int G, int C)
{
    __shared__ float s_acc[4 * 64 * 32];           // 32 KB, stride 32 (no pad)

    const int t    = threadIdx.x;
    const int w    = t >> 5;                       // warp = 32-col slice
    const int lane = t & 31;
    const int grp  = lane >> 3;                    // node group 0..3
    const int slot = lane & 7;                     // float4 slot 0..7
    const unsigned below = grp ? ((1u << (grp * 8)) - 1u) : 0u;

    const int g     = blockIdx.x / C;
    const int chunk = blockIdx.x % C;
    const int gbeg  = g_node_off[g];
    const int glen  = g_node_off[g + 1] - gbeg;
    const int cbeg  = gbeg + (int)((long long)glen * chunk / C);
    const int cend  = gbeg + (int)((long long)glen * (chunk + 1) / C);

    // zero accumulators
    float4* z = reinterpret_cast<float4*>(s_acc);
    #pragma unroll
    for (int i = t; i < 4 * 64 * 8; i += 128) z[i] = make_float4(0.f, 0.f, 0.f, 0.f);
    __syncthreads();

    float* acc = s_acc + w * 64 * 32;
    const float* fbase = feat + (size_t)w * 32 + (size_t)slot * 4;

    // pipeline (period-2 rotation):
    //   per iteration i at p: load_xy/feat(i+1); rmw(i); plan(i+1)
    // vv(i+1) is untouched until rmw(i+1) -> in flight for a full iteration.
    Meta M0, M1; Plan P0, P1; float4 V0[8], V1[8];
    int p = cbeg;
    if (p < cend) {
        load_xy(M0, xy, p, cend, G, lane);
        load_feat(V0, fbase, p, cend, grp);
        plan_batch(P0, M0, p, cend, lane, grp, below);
        for (;;) {
            int pn = p + 32;
            bool more = pn < cend;
            if (more) { load_xy(M1, xy, pn, cend, G, lane);
                        load_feat(V1, fbase, pn, cend, grp); }
            rmw_batch(acc, V0, P0, M0, grp, slot);
            if (!more) break;
            plan_batch(P1, M1, pn, cend, lane, grp, below);
            p = pn;

            pn = p + 32;
            more = pn < cend;
            if (more) { load_xy(M0, xy, pn, cend, G, lane);
                        load_feat(V0, fbase, pn, cend, grp); }
            rmw_batch(acc, V1, P1, M1, grp, slot);
            if (!more) break;
            plan_batch(P0, M0, pn, cend, lane, grp, below);
            p = pn;
        }
    }
    __syncwarp();

    // epilogue: each warp flushes its own 8KB slice via RED.v4
    float* dstw = out + (size_t)g * 64 * 128 + (size_t)w * 32;
    #pragma unroll
    for (int i = lane; i < 512; i += 32) {
        const int seg = i >> 3, q = i & 7;
        float4 a = *reinterpret_cast<float4*>(acc + seg * 32 + q * 4);
        asm volatile("red.global.add.v4.f32 [%0], {%1, %2, %3, %4};"
                     :: "l"(dstw + (size_t)seg * 128 + q * 4),
                        "f"(a.x), "f"(a.y), "f"(a.z), "f"(a.w)
                     : "memory");
    }
}

// ---------------- fallback path (round-2 kernel) ----------------
__device__ __forceinline__ int find_graph(const int* s_off, int B, int node) {
    int lo = 0, hi = B;
    while (hi - lo > 1) {
        int mid = (lo + hi) >> 1;
        if (s_off[mid] <= node) lo = mid; else hi = mid;
    }
    return lo;
}

__global__ void __launch_bounds__(256) spp_pool_fallback(
    const float* __restrict__ feat, const int* __restrict__ xy,
    float* __restrict__ out, int N, int D, int G, int B)
{
    extern __shared__ int s_off[];
    for (int i = threadIdx.x; i <= B; i += blockDim.x) s_off[i] = g_node_off[i];
    __syncthreads();

    const int lane   = threadIdx.x & 31;
    const int warp   = (blockIdx.x * blockDim.x + threadIdx.x) >> 5;
    const int nwarps = (gridDim.x * blockDim.x) >> 5;

    for (long long base = (long long)warp * 32; base < N;
         base += (long long)nwarps * 32) {
        long long mynode = base + lane;
        int nd = (mynode < N) ? (int)mynode : (N - 1);
        const int r  = __ldg(&xy[3 * nd + 0]);
        const int c  = __ldg(&xy[3 * nd + 1]);
        const int dv = __ldg(&xy[3 * nd + 2]);
        int gid = find_graph(s_off, B, nd);
        const int   myseg = (gid * G + r) * G + c;
        const float myinv = 1.0f / (float)dv;
        const int cnt = (N - base >= 32) ? 32 : (int)(N - base);

        for (int j = 0; j < cnt; ++j) {
            const int   seg = __shfl_sync(0xffffffffu, myseg, j);
            const float inv = __shfl_sync(0xffffffffu, myinv, j);
            const float* src = feat + ((size_t)(base + j)) * D;
            for (int d4 = lane; d4 * 4 < D; d4 += 32) {
                float4 v = __ldg(reinterpret_cast<const float4*>(src) + d4);
                v.x *= inv; v.y *= inv; v.z *= inv; v.w *= inv;
                float* dst = out + (size_t)seg * D + d4 * 4;
                asm volatile("red.global.add.v4.f32 [%0], {%1, %2, %3, %4};"
                             :: "l"(dst), "f"(v.x), "f"(v.y), "f"(v.z), "f"(v.w)
                             : "memory");
            }
        }
    }
}

extern "C" void kernel_launch(void* const* d_in, const int* in_sizes, int n_in,
                              void* d_out, int out_size) {
    const float* feat = (const float*)d_in[0];
    const int*   xy   = (const int*)d_in[1];
    const int*   bn   = (const int*)d_in[2];
    float*       out  = (float*)d_out;

    const int B = in_sizes[2];
    const int N = in_sizes[1] / 3;
    const int D = in_sizes[0] / N;
    const int S = out_size / D;        // B*G*G
    const int gg = S / B;
    int G = 1;
    while (G * G < gg) ++G;

    k_prefix<<<1, 32>>>(bn, B);

    // output accumulated via RED in both paths -> zero every replay
    cudaMemsetAsync(d_out, 0, (size_t)out_size * sizeof(float), 0);

    const bool fast = (D == 128) && (gg == 64) && (G == 8) &&
                      (S == B * 64) && (B <= 1024);

    if (fast) {
        int C = 704 / B;               // single wave at 5 CTAs/SM (B=64 -> 11)
        if (C < 1) C = 1;
        spp_pipe_kernel<<<B * C, 128>>>(feat, xy, out, G, C);
    } else {
        size_t smem = (size_t)(B + 1) * sizeof(int);
        long long batches = ((long long)N + 31) / 32;
        int blocks = (int)((batches + 7) / 8);
        if (blocks > 65535) blocks = 65535;
        spp_pool_fallback<<<blocks, 256, smem>>>(feat, xy, out, N, D, G, B);
    }
}